// round 5
// baseline (speedup 1.0000x reference)
#include <cuda_runtime.h>

// Problem constants
#define TT 16384
#define HH 100
#define HP 104          // padded h length (2 x 52, float4-aligned halves)
#define KS 52           // k-slice width per lane (half of HP)

// Hidden states [t][u] (row stride 100 floats, 16B-aligned rows)
__device__ float g_hs[TT * HH];

// ---------------------------------------------------------------------------
// Packed fp32x2 FMA (2 fp32 FMAs per instruction)
// ---------------------------------------------------------------------------
__device__ __forceinline__ float2 ffma2(float2 a, float2 b, float2 c) {
    float2 r;
    asm("fma.rn.f32x2 %0, %1, %2, %3;"
        : "=l"(reinterpret_cast<unsigned long long&>(r))
        : "l"(reinterpret_cast<unsigned long long&>(a)),
          "l"(reinterpret_cast<unsigned long long&>(b)),
          "l"(reinterpret_cast<unsigned long long&>(c)));
    return r;
}
__device__ __forceinline__ float ex2_approx(float x) {
    float r; asm("ex2.approx.f32 %0, %1;" : "=f"(r) : "f"(x)); return r;
}
__device__ __forceinline__ float rcp_approx(float x) {
    float r; asm("rcp.approx.f32 %0, %1;" : "=f"(r) : "f"(x)); return r;
}

#define LOG2E 1.4426950408889634f

// tanh(x) = 2*rcp(1+ex2(-2log2e*x)) - 1 (saturates correctly at +/-inf)
__device__ __forceinline__ float tanh_fast(float x) {
    float e = ex2_approx(-2.0f * LOG2E * x);
    return fmaf(2.0f, rcp_approx(1.0f + e), -1.0f);
}

// ---------------------------------------------------------------------------
// Fused kernel: sequential LSTM + output projection.
// ONE block, 800 threads = 25 warps = 100 units x 8 lanes.
//
// Lane octet o = tid&7 of unit u = tid>>3:
//   gate  g  = o>>1   (i,f,g,o order)
//   khalf kh = o&1    (k in [52*kh, 52*kh+52), h padded to 104 with zeros)
// Each lane: one gate row over a 52-wide slice in registers (26 float2).
// Per step: 13 LDS.128 + 26 FFMA2 (two 13-deep chains), ONE shfl_xor to
// merge k-halves, branch-free activation, 4 gather shfls, replicated c/h
// tail on all 8 lanes (predicate only on the stores). One barrier per step.
// 25 warps => ~6.25 warps/SMSP: issue demand exceeds the (shortened)
// critical path, so lockstep stalls are covered by other warps' issue.
// ---------------------------------------------------------------------------
__global__ void __launch_bounds__(800, 1)
k_lstm_fused(const float* __restrict__ x,
             const float* __restrict__ Whh,
             const float* __restrict__ Wih,
             const float* __restrict__ bih,
             const float* __restrict__ bhh,
             const float* __restrict__ Wlin,
             const float* __restrict__ blin,
             float* __restrict__ out) {
    __shared__ __align__(16) float sh[2][HP];  // h double buffer
    __shared__ float sWl[HH];                  // W_lin for projection tail
    __shared__ float sbl;

    const int tid = threadIdx.x;
    const int l   = tid & 31;
    const int o   = tid & 7;
    const int u   = tid >> 3;          // 0..99 exactly (800 threads)
    const int g   = o >> 1;
    const int kh  = o & 1;
    const int lb  = l & ~7;            // octet base lane within warp
    const int row = g * HH + u;

    // Branch-free activation constants (gate 2 -> tanh, else sigmoid)
    const float Kc = (g == 2) ? (-2.0f * LOG2E) : (-LOG2E);
    const float Ac = (g == 2) ? 2.0f : 1.0f;
    const float Bc = (g == 2) ? -1.0f : 0.0f;

    // Weight slice: wv[j] = W_hh[row][52*kh + 2j, +1], zero-padded past 100
    float2 wv[26];
    {
        const float* wr = Whh + row * HH;
        #pragma unroll
        for (int j = 0; j < 26; j++) {
            int k0 = KS * kh + 2 * j;
            float va = (k0     < HH) ? wr[k0]     : 0.0f;
            float vb = (k0 + 1 < HH) ? wr[k0 + 1] : 0.0f;
            wv[j] = make_float2(va, vb);
        }
    }
    const float wi0 = Wih[row * 3 + 0];
    const float wi1 = Wih[row * 3 + 1];
    const float wi2 = Wih[row * 3 + 2];
    const float bias = bih[row] + bhh[row];

    // Stage W_lin (+bias) for the projection tail; zero h buffers
    if (tid < HH) sWl[tid] = Wlin[tid];
    if (tid == 0) sbl = blin[0];
    for (int i = tid; i < 2 * HP; i += 800) (&sh[0][0])[i] = 0.0f;
    __syncthreads();

    // x prefetch registers (2-step effective depth; uniform-address LDG)
    float cx0 = x[0], cx1 = x[1], cx2 = x[2];
    float nx0 = x[3], nx1 = x[4], nx2 = x[5];

    float c = 0.0f;

    #pragma unroll 1
    for (int t = 0; t < TT; t++) {
        // Input contribution for this row
        float xg = fmaf(wi2, cx2, fmaf(wi1, cx1, fmaf(wi0, cx0, bias)));
        // rotate prefetch, issue load for t+2
        cx0 = nx0; cx1 = nx1; cx2 = nx2;
        {
            int tp = t + 2; if (tp > TT - 1) tp = TT - 1;
            const float* xp = x + tp * 3;
            nx0 = __ldg(xp); nx1 = __ldg(xp + 1); nx2 = __ldg(xp + 2);
        }

        // Partial dot over this lane's 52-wide h slice
        const float4* hp = reinterpret_cast<const float4*>(&sh[t & 1][0])
                         + kh * (KS / 4);
        float2 a0 = make_float2(0.0f, 0.0f);
        float2 a1 = make_float2(0.0f, 0.0f);
        #pragma unroll
        for (int j = 0; j < 13; j++) {
            float4 hv = hp[j];
            a0 = ffma2(make_float2(hv.x, hv.y), wv[2 * j],     a0);
            a1 = ffma2(make_float2(hv.z, hv.w), wv[2 * j + 1], a1);
        }
        float own = (a0.x + a1.x) + (a0.y + a1.y);

        // Merge the two k-halves (partner differs only in bit0 of lane)
        float rec = __shfl_xor_sync(0xffffffffu, own, 1);
        float gt  = own + rec + xg;

        // Branch-free activation of this lane's gate
        float ev = ex2_approx(Kc * gt);
        float av = fmaf(Ac, rcp_approx(1.0f + ev), Bc);

        // Gather i,f,g,o of this unit (octet-local lanes 0,2,4,6)
        float a_i = __shfl_sync(0xffffffffu, av, lb + 0);
        float a_f = __shfl_sync(0xffffffffu, av, lb + 2);
        float a_g = __shfl_sync(0xffffffffu, av, lb + 4);
        float a_o = __shfl_sync(0xffffffffu, av, lb + 6);

        // Replicated c/h update (identical on all 8 octet lanes)
        c = fmaf(a_f, c, a_i * a_g);
        float hn = a_o * tanh_fast(c);

        if (o == 0) {
            sh[(t & 1) ^ 1][u] = hn;
            g_hs[t * HH + u]   = hn;
        }
        __syncthreads();
    }

    // ---- projection tail: out[t] = sigmoid(sum_u hs[t][u]*Wl[u] + b) ----
    const float bl = sbl;
    for (int t = tid; t < TT; t += 800) {
        const float4* hr = reinterpret_cast<const float4*>(g_hs + t * HH);
        float s0 = 0.0f, s1 = 0.0f;
        #pragma unroll
        for (int j = 0; j < 25; j++) {
            float4 hv = hr[j];
            const float* wl = sWl + 4 * j;
            s0 = fmaf(hv.x, wl[0], s0);
            s1 = fmaf(hv.y, wl[1], s1);
            s0 = fmaf(hv.z, wl[2], s0);
            s1 = fmaf(hv.w, wl[3], s1);
        }
        float z = s0 + s1 + bl;
        out[t] = rcp_approx(1.0f + ex2_approx(-LOG2E * z));
    }
}

// ---------------------------------------------------------------------------
// Launch.  Inputs: input_x, W_ih, W_hh, b_ih, b_hh, W_lin, b_lin
// ---------------------------------------------------------------------------
extern "C" void kernel_launch(void* const* d_in, const int* in_sizes, int n_in,
                              void* d_out, int out_size) {
    const float* x    = (const float*)d_in[0];
    const float* Wih  = (const float*)d_in[1];
    const float* Whh  = (const float*)d_in[2];
    const float* bih  = (const float*)d_in[3];
    const float* bhh  = (const float*)d_in[4];
    const float* Wlin = (const float*)d_in[5];
    const float* blin = (const float*)d_in[6];
    float* out = (float*)d_out;

    (void)in_sizes; (void)n_in; (void)out_size;

    k_lstm_fused<<<1, 800>>>(x, Whh, Wih, bih, bhh, Wlin, blin, out);
}

// round 7
// speedup vs baseline: 1.8250x; 1.8250x over previous
#include <cuda_runtime.h>

// Problem constants
#define TT 16384
#define HH 100

// Hidden states [t][u]
__device__ float g_hs[TT * HH];

// ---------------------------------------------------------------------------
// Packed fp32x2 FMA (2 fp32 FMAs per instruction)
// ---------------------------------------------------------------------------
__device__ __forceinline__ float2 ffma2(float2 a, float2 b, float2 c) {
    float2 r;
    asm("fma.rn.f32x2 %0, %1, %2, %3;"
        : "=l"(reinterpret_cast<unsigned long long&>(r))
        : "l"(reinterpret_cast<unsigned long long&>(a)),
          "l"(reinterpret_cast<unsigned long long&>(b)),
          "l"(reinterpret_cast<unsigned long long&>(c)));
    return r;
}
__device__ __forceinline__ float2 fadd2(float2 a, float2 b) {
    float2 r;
    asm("add.rn.f32x2 %0, %1, %2;"
        : "=l"(reinterpret_cast<unsigned long long&>(r))
        : "l"(reinterpret_cast<unsigned long long&>(a)),
          "l"(reinterpret_cast<unsigned long long&>(b)));
    return r;
}
__device__ __forceinline__ float ex2_approx(float x) {
    float r; asm("ex2.approx.f32 %0, %1;" : "=f"(r) : "f"(x)); return r;
}
__device__ __forceinline__ float rcp_approx(float x) {
    float r; asm("rcp.approx.f32 %0, %1;" : "=f"(r) : "f"(x)); return r;
}

#define LOG2E 1.4426950408889634f

__device__ __forceinline__ float tanh_fast(float x) {
    float e = ex2_approx(-2.0f * LOG2E * x);
    return fmaf(2.0f, rcp_approx(1.0f + e), -1.0f);
}

// ---------------------------------------------------------------------------
// Fused LSTM + projection. ONE block, 200 threads (6.25 warps).
// Thread pair (2u, 2u+1) handles unit u:
//   even thread: gate rows i (u), f (100+u)          -> both sigmoid
//   odd  thread: gate rows g (200+u), o (300+u)      -> tanh, sigmoid
// Each thread keeps BOTH full 100-wide W_hh rows in registers (200 regs;
// at 200 threads the HW cap is 255 -> no spill). Per step: 25 broadcast
// LDS.128 + 100 FFMA2 in 4 independent 25-deep chains (sustains the
// 2-FFMA2/cyc SM rate), two activations, ONE shfl_xor pair-exchange
// (x2 values), replicated c/h tail, one barrier.
// Exactly 625 FFMA2/step across the block = the fp32 FMA-pipe floor, with
// warp count (and thus every warp-scaled phase) cut from 13 to 6.25.
// ---------------------------------------------------------------------------
__global__ void __launch_bounds__(200, 1)
k_lstm_fused(const float* __restrict__ x,
             const float* __restrict__ Whh,
             const float* __restrict__ Wih,
             const float* __restrict__ bih,
             const float* __restrict__ bhh,
             const float* __restrict__ Wlin,
             const float* __restrict__ blin,
             float* __restrict__ out) {
    extern __shared__ __align__(16) float sx[];        // [TT*3] input (192 KB)
    __shared__ __align__(16) float sh[2][HH];          // h double buffer
    __shared__ float sWl[HH];
    __shared__ float sbl;

    const int tid = threadIdx.x;          // 0..199
    const int odd = tid & 1;
    const int u   = tid >> 1;             // 0..99
    // Warp 6 holds only threads 192..199 (lanes 0..7)
    const unsigned mask = (tid >= 192) ? 0x000000FFu : 0xFFFFFFFFu;

    const int r0 = odd * 2 * HH + u;      // even: i-row, odd: g-row
    const int r1 = r0 + HH;               // even: f-row, odd: o-row

    // Activation constants. slot0: even->sigmoid, odd->tanh. slot1: sigmoid.
    const float K0 = odd ? (-2.0f * LOG2E) : (-LOG2E);
    const float A0 = odd ? 2.0f : 1.0f;
    const float B0 = odd ? -1.0f : 0.0f;

    // Both weight rows -> registers (2 x 50 float2 = 200 regs)
    float2 w0[50], w1[50];
    {
        const float2* p0 = reinterpret_cast<const float2*>(Whh + r0 * HH);
        const float2* p1 = reinterpret_cast<const float2*>(Whh + r1 * HH);
        #pragma unroll
        for (int i = 0; i < 50; i++) { w0[i] = p0[i]; w1[i] = p1[i]; }
    }
    const float wa0 = Wih[r0 * 3], wa1 = Wih[r0 * 3 + 1], wa2 = Wih[r0 * 3 + 2];
    const float wb0 = Wih[r1 * 3], wb1 = Wih[r1 * 3 + 1], wb2 = Wih[r1 * 3 + 2];
    const float bias0 = bih[r0] + bhh[r0];
    const float bias1 = bih[r1] + bhh[r1];

    // Preload x into SMEM (coalesced float4); stage W_lin; zero h buffers
    {
        const float4* xs = reinterpret_cast<const float4*>(x);
        float4* xd = reinterpret_cast<float4*>(sx);
        for (int i = tid; i < TT * 3 / 4; i += 200) xd[i] = xs[i];
    }
    if (tid < HH) sWl[tid] = Wlin[tid];
    if (tid == 0) sbl = blin[0];
    if (tid < 2 * HH) (&sh[0][0])[tid] = 0.0f;
    __syncthreads();

    float c = 0.0f;
    const float* xr = sx;

    #pragma unroll 1
    for (int t = 0; t < TT; t++, xr += 3) {
        // Input contributions for both rows (3 broadcast LDS.32, 6 FFMA)
        const float xv0 = xr[0], xv1 = xr[1], xv2 = xr[2];
        float xg0 = fmaf(wa2, xv2, fmaf(wa1, xv1, fmaf(wa0, xv0, bias0)));
        float xg1 = fmaf(wb2, xv2, fmaf(wb1, xv1, fmaf(wb0, xv0, bias1)));

        // Dual 100-wide dot products: 25 LDS.128 + 100 FFMA2 (4 indep chains)
        const float4* hp = reinterpret_cast<const float4*>(&sh[t & 1][0]);
        float2 a00 = make_float2(xg0, 0.0f), a01 = make_float2(0.0f, 0.0f);
        float2 a10 = make_float2(xg1, 0.0f), a11 = make_float2(0.0f, 0.0f);
        #pragma unroll
        for (int i = 0; i < 25; i++) {
            float4 hv = hp[i];
            float2 lo = make_float2(hv.x, hv.y);
            float2 hi = make_float2(hv.z, hv.w);
            a00 = ffma2(lo, w0[2 * i],     a00);
            a01 = ffma2(hi, w0[2 * i + 1], a01);
            a10 = ffma2(lo, w1[2 * i],     a10);
            a11 = ffma2(hi, w1[2 * i + 1], a11);
        }
        float2 s0 = fadd2(a00, a01);
        float2 s1 = fadd2(a10, a11);
        float gt0 = s0.x + s0.y;
        float gt1 = s1.x + s1.y;

        // Activations (branch-free, per-slot constants)
        float e0 = ex2_approx(K0 * gt0);
        float a0 = fmaf(A0, rcp_approx(1.0f + e0), B0);
        float e1 = ex2_approx(-LOG2E * gt1);
        float a1 = rcp_approx(1.0f + e1);

        // Pair exchange: partner differs in lane bit 0
        float p0 = __shfl_xor_sync(mask, a0, 1);
        float p1 = __shfl_xor_sync(mask, a1, 1);
        // even: i=a0 f=a1 g=p0 o=p1 ; odd: i=p0 f=p1 g=a0 o=a1
        float ai = odd ? p0 : a0;
        float af = odd ? p1 : a1;
        float ag = odd ? a0 : p0;
        float ao = odd ? a1 : p1;

        // Replicated c/h update (identical on both pair threads)
        c = fmaf(af, c, ai * ag);
        float hn = ao * tanh_fast(c);

        if (!odd) {
            sh[(t & 1) ^ 1][u] = hn;
            g_hs[t * HH + u]   = hn;
        }
        __syncthreads();
    }

    // ---- projection tail: out[t] = sigmoid(sum_u hs[t][u]*Wl[u] + b) ----
    const float bl = sbl;
    for (int t = tid; t < TT; t += 200) {
        const float4* hr = reinterpret_cast<const float4*>(g_hs + t * HH);
        float s0 = 0.0f, s1 = 0.0f;
        #pragma unroll
        for (int j = 0; j < 25; j++) {
            float4 hv = hr[j];
            const float* wl = sWl + 4 * j;
            s0 = fmaf(hv.x, wl[0], s0);
            s1 = fmaf(hv.y, wl[1], s1);
            s0 = fmaf(hv.z, wl[2], s0);
            s1 = fmaf(hv.w, wl[3], s1);
        }
        float z = s0 + s1 + bl;
        out[t] = rcp_approx(1.0f + ex2_approx(-LOG2E * z));
    }
}

// ---------------------------------------------------------------------------
// Launch.  Inputs: input_x, W_ih, W_hh, b_ih, b_hh, W_lin, b_lin
// ---------------------------------------------------------------------------
extern "C" void kernel_launch(void* const* d_in, const int* in_sizes, int n_in,
                              void* d_out, int out_size) {
    const float* x    = (const float*)d_in[0];
    const float* Wih  = (const float*)d_in[1];
    const float* Whh  = (const float*)d_in[2];
    const float* bih  = (const float*)d_in[3];
    const float* bhh  = (const float*)d_in[4];
    const float* Wlin = (const float*)d_in[5];
    const float* blin = (const float*)d_in[6];
    float* out = (float*)d_out;

    (void)in_sizes; (void)n_in; (void)out_size;

    const int smem_bytes = TT * 3 * (int)sizeof(float);   // 192 KB (x only)
    static bool attr_set = false;
    if (!attr_set) {
        cudaFuncSetAttribute(k_lstm_fused,
                             cudaFuncAttributeMaxDynamicSharedMemorySize,
                             smem_bytes);
        attr_set = true;
    }

    k_lstm_fused<<<1, 200, smem_bytes>>>(x, Whh, Wih, bih, bhh,
                                         Wlin, blin, out);
}